// round 3
// baseline (speedup 1.0000x reference)
#include <cuda_runtime.h>
#include <cstdint>

#define N_NODES 100000
#define N_EDGES 1600000
#define D 128
#define EF 32

// 51.2 MB scratch accumulator: x = h + agg
__device__ float g_x[(size_t)N_NODES * D];

typedef unsigned long long u64;

__device__ __forceinline__ u64 pack2(float lo, float hi) {
    u64 r; asm("mov.b64 %0, {%1, %2};" : "=l"(r) : "f"(lo), "f"(hi)); return r;
}
__device__ __forceinline__ void unpack2(u64 v, float &lo, float &hi) {
    asm("mov.b64 {%0, %1}, %2;" : "=f"(lo), "=f"(hi) : "l"(v));
}
// Blackwell packed f32x2 FMA: d = a*b + c (two lanes per instruction)
__device__ __forceinline__ u64 ffma2(u64 a, u64 b, u64 c) {
    u64 d; asm("fma.rn.f32x2 %0, %1, %2, %3;" : "=l"(d) : "l"(a), "l"(b), "l"(c));
    return d;
}
// Vectorized fire-and-forget global reduction (sm_90+)
__device__ __forceinline__ void red_add_v4(float* p, float a, float b, float c, float d) {
    asm volatile("red.global.add.v4.f32 [%0], {%1,%2,%3,%4};"
                 :: "l"(p), "f"(a), "f"(b), "f"(c), "f"(d) : "memory");
}

// ---------------------------------------------------------------------------
// Kernel 1: g_x = h   (exact: N*D/4 = 3.2M float4, grid*block covers exactly)
// ---------------------------------------------------------------------------
__global__ void k_init(const float4* __restrict__ h4) {
    int i = blockIdx.x * blockDim.x + threadIdx.x;
    ((float4*)g_x)[i] = h4[i];
}

// ---------------------------------------------------------------------------
// Kernel 2: per-edge  msg = h[src] + (edge_attr @ W_e + b_e);  g_x[dst] += msg
// Warp processes 8 edges at once so each W_e row (LDS.128, 512B/warp) feeds
// 16 FFMA2 instructions -> FFMA-bound, not smem-bound.
// E = 1.6M = 25000 blocks * 8 warps * 8 edges exactly.
// ---------------------------------------------------------------------------
__global__ void __launch_bounds__(256) k_edges(
    const float* __restrict__ h, const int2* __restrict__ eidx,
    const float* __restrict__ ea, const float* __restrict__ We,
    const float* __restrict__ be)
{
    __shared__ __align__(16) float sWe[EF * D];   // 16 KB
    __shared__ u64 sea[8][8][EF];                 // 16 KB, edge_attr duplicated (v,v)

    int tid = threadIdx.x;
    for (int i = tid; i < EF * D; i += 256) sWe[i] = We[i];
    __syncthreads();

    int w = tid >> 5, lane = tid & 31;
    int ebase = (blockIdx.x * 8 + w) * 8;

    // stage edge_attr for 8 edges, duplicated for f32x2 broadcast
    #pragma unroll
    for (int j = 0; j < 8; j++) {
        float a = ea[(size_t)(ebase + j) * EF + lane];
        sea[w][j][lane] = pack2(a, a);
    }
    __syncwarp();

    float4 bv = *(const float4*)(be + lane * 4);
    u64 acc[8][2];
    int dsts[8];
    #pragma unroll
    for (int j = 0; j < 8; j++) {
        int2 e = eidx[ebase + j];              // uniform across warp -> broadcast
        dsts[j] = e.y;
        float4 hv = *(const float4*)(h + (size_t)e.x * D + lane * 4);
        acc[j][0] = pack2(hv.x + bv.x, hv.y + bv.y);
        acc[j][1] = pack2(hv.z + bv.z, hv.w + bv.w);
    }

    const ulonglong2* Wp = (const ulonglong2*)sWe;
    #pragma unroll
    for (int k = 0; k < EF; k++) {
        ulonglong2 wv = Wp[k * 32 + lane];     // W_e[k][lane*4 .. +3]
        #pragma unroll
        for (int j = 0; j < 8; j++) {
            u64 a2 = sea[w][j][k];             // broadcast LDS.64
            acc[j][0] = ffma2(a2, wv.x, acc[j][0]);
            acc[j][1] = ffma2(a2, wv.y, acc[j][1]);
        }
    }

    #pragma unroll
    for (int j = 0; j < 8; j++) {
        float x0, x1, x2, x3;
        unpack2(acc[j][0], x0, x1);
        unpack2(acc[j][1], x2, x3);
        red_add_v4(g_x + (size_t)dsts[j] * D + lane * 4, x0, x1, x2, x3);
    }
}

// ---------------------------------------------------------------------------
// Kernel 3: out = gelu_exact(x @ W1 + b1) @ W2 + b2, x in g_x.
// Block = 256 thr, tile = 64 rows x 128 cols. Each thread: 8 rows x 4 cols
// (8x2 f32x2 accumulators). W rows read via LDG.128 (L1-resident, 128 KB).
// x tile staged in dynamic smem duplicated (v,v) for FFMA2 broadcast.
// ---------------------------------------------------------------------------
__global__ void __launch_bounds__(256) k_mlp(
    const float* __restrict__ W1, const float* __restrict__ b1,
    const float* __restrict__ W2, const float* __restrict__ b2,
    float* __restrict__ out)
{
    extern __shared__ u64 xsd[];               // [64][128] u64 = 64 KB
    int tid = threadIdx.x;
    int lane = tid & 31, w = tid >> 5;
    int row0 = blockIdx.x * 64;

    // load x tile, duplicated
    for (int f = tid; f < 64 * 32; f += 256) {
        int r = f >> 5, c4 = f & 31;
        float4 v = make_float4(0.f, 0.f, 0.f, 0.f);
        if (row0 + r < N_NODES)
            v = ((const float4*)g_x)[(size_t)(row0 + r) * 32 + c4];
        u64* p = xsd + r * 128 + c4 * 4;
        p[0] = pack2(v.x, v.x); p[1] = pack2(v.y, v.y);
        p[2] = pack2(v.z, v.z); p[3] = pack2(v.w, v.w);
    }
    __syncthreads();

    u64 acc[8][2];
    {
        float4 bv = *(const float4*)(b1 + lane * 4);
        #pragma unroll
        for (int i = 0; i < 8; i++) {
            acc[i][0] = pack2(bv.x, bv.y);
            acc[i][1] = pack2(bv.z, bv.w);
        }
    }
    #pragma unroll 4
    for (int k = 0; k < D; k++) {
        ulonglong2 wv = *(const ulonglong2*)(W1 + (size_t)k * D + lane * 4);
        #pragma unroll
        for (int i = 0; i < 8; i++) {
            u64 xv = xsd[(w * 8 + i) * 128 + k];
            acc[i][0] = ffma2(xv, wv.x, acc[i][0]);
            acc[i][1] = ffma2(xv, wv.y, acc[i][1]);
        }
    }
    __syncthreads();   // all xsd reads complete before overwrite

    // exact GELU: x * Phi(x), store t duplicated back to xsd
    #pragma unroll
    for (int i = 0; i < 8; i++) {
        float t0, t1, t2, t3;
        unpack2(acc[i][0], t0, t1);
        unpack2(acc[i][1], t2, t3);
        t0 *= normcdff(t0); t1 *= normcdff(t1);
        t2 *= normcdff(t2); t3 *= normcdff(t3);
        u64* p = xsd + (w * 8 + i) * 128 + lane * 4;
        p[0] = pack2(t0, t0); p[1] = pack2(t1, t1);
        p[2] = pack2(t2, t2); p[3] = pack2(t3, t3);
    }
    __syncthreads();

    {
        float4 bv = *(const float4*)(b2 + lane * 4);
        #pragma unroll
        for (int i = 0; i < 8; i++) {
            acc[i][0] = pack2(bv.x, bv.y);
            acc[i][1] = pack2(bv.z, bv.w);
        }
    }
    #pragma unroll 4
    for (int k = 0; k < D; k++) {
        ulonglong2 wv = *(const ulonglong2*)(W2 + (size_t)k * D + lane * 4);
        #pragma unroll
        for (int i = 0; i < 8; i++) {
            u64 xv = xsd[(w * 8 + i) * 128 + k];
            acc[i][0] = ffma2(xv, wv.x, acc[i][0]);
            acc[i][1] = ffma2(xv, wv.y, acc[i][1]);
        }
    }

    #pragma unroll
    for (int i = 0; i < 8; i++) {
        int r = row0 + w * 8 + i;
        if (r < N_NODES) {
            float o0, o1, o2, o3;
            unpack2(acc[i][0], o0, o1);
            unpack2(acc[i][1], o2, o3);
            *(float4*)(out + (size_t)r * D + lane * 4) = make_float4(o0, o1, o2, o3);
        }
    }
}

// ---------------------------------------------------------------------------
extern "C" void kernel_launch(void* const* d_in, const int* in_sizes, int n_in,
                              void* d_out, int out_size) {
    const float* h  = (const float*)d_in[0];
    const int2* ei  = (const int2*)d_in[1];
    const float* ea = (const float*)d_in[2];
    const float* We = (const float*)d_in[3];
    const float* be = (const float*)d_in[4];
    const float* W1 = (const float*)d_in[5];
    const float* b1 = (const float*)d_in[6];
    const float* W2 = (const float*)d_in[7];
    const float* b2 = (const float*)d_in[8];
    float* out = (float*)d_out;

    cudaFuncSetAttribute(k_mlp, cudaFuncAttributeMaxDynamicSharedMemorySize, 65536);

    k_init<<<(N_NODES * D / 4) / 256, 256>>>((const float4*)h);
    k_edges<<<N_EDGES / 64, 256>>>(h, ei, ea, We, be);
    k_mlp<<<(N_NODES + 63) / 64, 256, 65536>>>(W1, b1, W2, b2, out);
}

// round 7
// speedup vs baseline: 1.3253x; 1.3253x over previous
#include <cuda_runtime.h>
#include <cstdint>

#define N_NODES 100000
#define N_EDGES 1600000
#define D 128
#define EF 32

// scratch (no allocations allowed): x = h + agg, CSR structures
__device__ float g_x[(size_t)N_NODES * D];        // 51.2 MB
__device__ int   g_cnt[N_NODES];
__device__ int   g_rowptr[N_NODES + 1];
__device__ int   g_cursor[N_NODES];
__device__ int2  g_csr[N_EDGES];                  // (src, edge_id) bucketed by dst

typedef unsigned long long u64;

__device__ __forceinline__ u64 pack2(float lo, float hi) {
    u64 r; asm("mov.b64 %0, {%1, %2};" : "=l"(r) : "f"(lo), "f"(hi)); return r;
}
__device__ __forceinline__ void unpack2(u64 v, float &lo, float &hi) {
    asm("mov.b64 {%0, %1}, %2;" : "=f"(lo), "=f"(hi) : "l"(v));
}
__device__ __forceinline__ u64 ffma2(u64 a, u64 b, u64 c) {
    u64 d; asm("fma.rn.f32x2 %0, %1, %2, %3;" : "=l"(d) : "l"(a), "l"(b), "l"(c));
    return d;
}

// ---------------------------------------------------------------------------
// CSR build: zero counts -> histogram -> scan -> bucket scatter
// ---------------------------------------------------------------------------
__global__ void k_zero() {
    int i = blockIdx.x * blockDim.x + threadIdx.x;
    if (i < N_NODES) g_cnt[i] = 0;
}

__global__ void k_hist(const int2* __restrict__ eidx) {
    int i = blockIdx.x * blockDim.x + threadIdx.x;   // exactly N_EDGES threads
    atomicAdd(&g_cnt[eidx[i].y], 1);                 // compiles to RED (no return)
}

// single-block exclusive scan of g_cnt -> g_rowptr / g_cursor
#define SCAN_CHUNK 98
__global__ void k_scan() {
    __shared__ int ssum[1024];
    int t = threadIdx.x;
    int base = t * SCAN_CHUNK;
    int s = 0;
    for (int j = 0; j < SCAN_CHUNK; j++) {
        int idx = base + j;
        if (idx < N_NODES) s += g_cnt[idx];
    }
    ssum[t] = s;
    __syncthreads();
    for (int off = 1; off < 1024; off <<= 1) {
        int v = 0;
        if (t >= off) v = ssum[t - off];
        __syncthreads();
        ssum[t] += v;
        __syncthreads();
    }
    int run = (t == 0) ? 0 : ssum[t - 1];
    for (int j = 0; j < SCAN_CHUNK; j++) {
        int idx = base + j;
        if (idx < N_NODES) {
            g_rowptr[idx] = run;
            g_cursor[idx] = run;
            run += g_cnt[idx];
        }
    }
    if (t == 1023) g_rowptr[N_NODES] = ssum[1023];
}

__global__ void k_scatter(const int2* __restrict__ eidx) {
    int i = blockIdx.x * blockDim.x + threadIdx.x;   // exactly N_EDGES threads
    int2 e = eidx[i];
    int pos = atomicAdd(&g_cursor[e.y], 1);
    g_csr[pos] = make_int2(e.x, i);
}

// ---------------------------------------------------------------------------
// Aggregation (one warp per dst, no atomics):
//   x[dst] = h[dst] + Sum h[src] + (Sum edge_attr) @ W_e + deg * b_e
// ---------------------------------------------------------------------------
__global__ void __launch_bounds__(256) k_agg(
    const float4* __restrict__ h4, const float* __restrict__ ea,
    const float* __restrict__ We, const float* __restrict__ be)
{
    __shared__ __align__(16) float4 sWe[EF * 32];    // 16 KB
    __shared__ float4 sbe[32];

    int tid = threadIdx.x;
    for (int i = tid; i < EF * 32; i += 256) sWe[i] = ((const float4*)We)[i];
    if (tid < 32) sbe[tid] = ((const float4*)be)[tid];
    __syncthreads();

    int w = tid >> 5, lane = tid & 31;
    int dst = blockIdx.x * 8 + w;                    // grid covers exactly N_NODES
    int start = g_rowptr[dst];
    int end   = g_rowptr[dst + 1];

    float4 acc = h4[(size_t)dst * 32 + lane];        // includes self term
    float accA = 0.f;

    int j = start;
    for (; j + 4 <= end; j += 4) {                   // MLP=4 gather batching
        int2 c0 = g_csr[j + 0], c1 = g_csr[j + 1];
        int2 c2 = g_csr[j + 2], c3 = g_csr[j + 3];
        float4 v0 = h4[(size_t)c0.x * 32 + lane];
        float4 v1 = h4[(size_t)c1.x * 32 + lane];
        float4 v2 = h4[(size_t)c2.x * 32 + lane];
        float4 v3 = h4[(size_t)c3.x * 32 + lane];
        float a0 = ea[(size_t)c0.y * EF + lane];
        float a1 = ea[(size_t)c1.y * EF + lane];
        float a2 = ea[(size_t)c2.y * EF + lane];
        float a3 = ea[(size_t)c3.y * EF + lane];
        acc.x += (v0.x + v1.x) + (v2.x + v3.x);
        acc.y += (v0.y + v1.y) + (v2.y + v3.y);
        acc.z += (v0.z + v1.z) + (v2.z + v3.z);
        acc.w += (v0.w + v1.w) + (v2.w + v3.w);
        accA  += (a0 + a1) + (a2 + a3);
    }
    for (; j < end; ++j) {
        int2 c = g_csr[j];
        float4 v = h4[(size_t)c.x * 32 + lane];
        acc.x += v.x; acc.y += v.y; acc.z += v.z; acc.w += v.w;
        accA  += ea[(size_t)c.y * EF + lane];
    }

    // tiny per-node GEMM: accA (32-vec, distributed lane k) @ W_e[:, lane cols]
    #pragma unroll
    for (int k = 0; k < EF; k++) {
        float a = __shfl_sync(0xffffffffu, accA, k);
        float4 wv = sWe[k * 32 + lane];
        acc.x += a * wv.x; acc.y += a * wv.y;
        acc.z += a * wv.z; acc.w += a * wv.w;
    }
    float fd = (float)(end - start);
    float4 bv = sbe[lane];
    acc.x += fd * bv.x; acc.y += fd * bv.y;
    acc.z += fd * bv.z; acc.w += fd * bv.w;

    ((float4*)g_x)[(size_t)dst * 32 + lane] = acc;
}

// ---------------------------------------------------------------------------
// MLP: out = gelu_exact(x @ W1 + b1) @ W2 + b2   (unchanged from R2)
// ---------------------------------------------------------------------------
__global__ void __launch_bounds__(256) k_mlp(
    const float* __restrict__ W1, const float* __restrict__ b1,
    const float* __restrict__ W2, const float* __restrict__ b2,
    float* __restrict__ out)
{
    extern __shared__ u64 xsd[];               // [64][128] u64 = 64 KB
    int tid = threadIdx.x;
    int lane = tid & 31, w = tid >> 5;
    int row0 = blockIdx.x * 64;

    for (int f = tid; f < 64 * 32; f += 256) {
        int r = f >> 5, c4 = f & 31;
        float4 v = make_float4(0.f, 0.f, 0.f, 0.f);
        if (row0 + r < N_NODES)
            v = ((const float4*)g_x)[(size_t)(row0 + r) * 32 + c4];
        u64* p = xsd + r * 128 + c4 * 4;
        p[0] = pack2(v.x, v.x); p[1] = pack2(v.y, v.y);
        p[2] = pack2(v.z, v.z); p[3] = pack2(v.w, v.w);
    }
    __syncthreads();

    u64 acc[8][2];
    {
        float4 bv = *(const float4*)(b1 + lane * 4);
        #pragma unroll
        for (int i = 0; i < 8; i++) {
            acc[i][0] = pack2(bv.x, bv.y);
            acc[i][1] = pack2(bv.z, bv.w);
        }
    }
    #pragma unroll 4
    for (int k = 0; k < D; k++) {
        ulonglong2 wv = *(const ulonglong2*)(W1 + (size_t)k * D + lane * 4);
        #pragma unroll
        for (int i = 0; i < 8; i++) {
            u64 xv = xsd[(w * 8 + i) * 128 + k];
            acc[i][0] = ffma2(xv, wv.x, acc[i][0]);
            acc[i][1] = ffma2(xv, wv.y, acc[i][1]);
        }
    }
    __syncthreads();

    #pragma unroll
    for (int i = 0; i < 8; i++) {
        float t0, t1, t2, t3;
        unpack2(acc[i][0], t0, t1);
        unpack2(acc[i][1], t2, t3);
        t0 *= normcdff(t0); t1 *= normcdff(t1);
        t2 *= normcdff(t2); t3 *= normcdff(t3);
        u64* p = xsd + (w * 8 + i) * 128 + lane * 4;
        p[0] = pack2(t0, t0); p[1] = pack2(t1, t1);
        p[2] = pack2(t2, t2); p[3] = pack2(t3, t3);
    }
    __syncthreads();

    {
        float4 bv = *(const float4*)(b2 + lane * 4);
        #pragma unroll
        for (int i = 0; i < 8; i++) {
            acc[i][0] = pack2(bv.x, bv.y);
            acc[i][1] = pack2(bv.z, bv.w);
        }
    }
    #pragma unroll 4
    for (int k = 0; k < D; k++) {
        ulonglong2 wv = *(const ulonglong2*)(W2 + (size_t)k * D + lane * 4);
        #pragma unroll
        for (int i = 0; i < 8; i++) {
            u64 xv = xsd[(w * 8 + i) * 128 + k];
            acc[i][0] = ffma2(xv, wv.x, acc[i][0]);
            acc[i][1] = ffma2(xv, wv.y, acc[i][1]);
        }
    }

    #pragma unroll
    for (int i = 0; i < 8; i++) {
        int r = row0 + w * 8 + i;
        if (r < N_NODES) {
            float o0, o1, o2, o3;
            unpack2(acc[i][0], o0, o1);
            unpack2(acc[i][1], o2, o3);
            *(float4*)(out + (size_t)r * D + lane * 4) = make_float4(o0, o1, o2, o3);
        }
    }
}

// ---------------------------------------------------------------------------
extern "C" void kernel_launch(void* const* d_in, const int* in_sizes, int n_in,
                              void* d_out, int out_size) {
    const float* h  = (const float*)d_in[0];
    const int2* ei  = (const int2*)d_in[1];
    const float* ea = (const float*)d_in[2];
    const float* We = (const float*)d_in[3];
    const float* be = (const float*)d_in[4];
    const float* W1 = (const float*)d_in[5];
    const float* b1 = (const float*)d_in[6];
    const float* W2 = (const float*)d_in[7];
    const float* b2 = (const float*)d_in[8];
    float* out = (float*)d_out;

    cudaFuncSetAttribute(k_mlp, cudaFuncAttributeMaxDynamicSharedMemorySize, 65536);

    k_zero<<<(N_NODES + 1023) / 1024, 1024>>>();
    k_hist<<<N_EDGES / 256, 256>>>(ei);
    k_scan<<<1, 1024>>>();
    k_scatter<<<N_EDGES / 256, 256>>>(ei);
    k_agg<<<N_NODES / 8, 256>>>((const float4*)h, ea, We, be);
    k_mlp<<<(N_NODES + 63) / 64, 256, 65536>>>(W1, b1, W2, b2, out);
}